// round 14
// baseline (speedup 1.0000x reference)
#include <cuda_runtime.h>
#include <cuda_fp16.h>
#include <math.h>
#include <stdint.h>

#define B_  8192
#define IN_ 1024
#define H_  2048
#define NH_ 4
#define HD_ 512
#define EPS_ 1e-5f

// ---------------------------------------------------------------------------
// Device scratch (allocation-free rule)
// ---------------------------------------------------------------------------
// fp16 activations / intermediates
__device__ __align__(128) __half g_xs_h[(size_t)B_ * IN_];   // x fp16
__device__ __align__(128) __half g_hs_h[(size_t)B_ * H_];    // h_prev fp16
__device__ __align__(128) __half g_xp_h[(size_t)B_ * H_];    // x_proj fp16
__device__ __align__(128) __half g_q_h [(size_t)B_ * H_];    // q fp16 -> gate fp16
__device__ __align__(128) __half g_at_h[(size_t)B_ * H_];    // attn fp16
__device__ __align__(128) __half g_ag_h[(size_t)B_ * H_];    // attn_gelu fp16

// fp16 weights
__device__ __align__(128) __half g_wp_h[(size_t)H_ * IN_];
__device__ __align__(128) __half g_wq_h[(size_t)H_ * H_];
__device__ __align__(128) __half g_wo_h[(size_t)H_ * H_];
__device__ __align__(128) __half g_wg_h[(size_t)H_ * 2 * H_];

// ---------------------------------------------------------------------------
// PTX helpers (base-target-safe)
// ---------------------------------------------------------------------------
__device__ __forceinline__ uint32_t smem_u32(const void* p) {
    uint32_t a;
    asm("{ .reg .u64 t; cvta.to.shared.u64 t, %1; cvt.u32.u64 %0, t; }" : "=r"(a) : "l"(p));
    return a;
}

#define CP_ASYNC16(sa, ga) \
    asm volatile("cp.async.cg.shared.global [%0], [%1], 16;\n" :: "r"(sa), "l"(ga))
#define CP_COMMIT()  asm volatile("cp.async.commit_group;\n" ::: "memory")

#define LDSM_X4(r0, r1, r2, r3, addr) \
    asm volatile("ldmatrix.sync.aligned.m8n8.x4.shared.b16 {%0,%1,%2,%3}, [%4];" \
        : "=r"(r0), "=r"(r1), "=r"(r2), "=r"(r3) : "r"(addr))

#define MMA_F16(c0, c1, c2, c3, a0, a1, a2, a3, b0, b1) \
    asm volatile("mma.sync.aligned.m16n8k16.row.col.f32.f16.f16.f32 " \
        "{%0,%1,%2,%3}, {%4,%5,%6,%7}, {%8,%9}, {%0,%1,%2,%3};" \
        : "+f"(c0), "+f"(c1), "+f"(c2), "+f"(c3) \
        : "r"(a0), "r"(a1), "r"(a2), "r"(a3), "r"(b0), "r"(b1))

// ---------------------------------------------------------------------------
// SMEM: per stage: A 128x64 fp16, B 128x64 fp16, row stride 72 elems (144B).
// 3 stages = 108 KB -> 2 CTA/SM.
// ---------------------------------------------------------------------------
#define SSTR 72
#define T_ELEMS (128 * SSTR)               // 9216
#define OFF_A 0
#define OFF_B T_ELEMS
#define STAGE_ELEMS (2 * T_ELEMS)          // 18432
#define NSTAGE 3
#define SMEM_BYTES (NSTAGE * STAGE_ELEMS * 2)   // 110592

// ---------------------------------------------------------------------------
// GEMM body: CTA 128x128, 8 warps (warp tile 64x32), K-chunk 64, 3 stages.
// ---------------------------------------------------------------------------
template<int ACT, int OUTMODE>   // OUTMODE: 0 fp32, 1 both, 2 fp16
__device__ __forceinline__ void gemm_body(
    const __half* __restrict__ a0h, const __half* __restrict__ a1h, int Ks,
    const __half* __restrict__ bhp,
    const float* __restrict__ bias, float* __restrict__ C,
    __half* __restrict__ ohi,
    int M, int N, int K, int bm, int bn)
{
    extern __shared__ __align__(128) char smem[];
    const uint32_t sbase = smem_u32(smem);
    const int tid  = threadIdx.x;
    const int warp = tid >> 5;
    const int lane = tid & 31;
    const int wm = (warp >> 2) * 64;       // 0 or 64
    const int wn = (warp & 3) * 32;        // 0..96

    float acc[4][4][4];
#pragma unroll
    for (int i = 0; i < 4; i++)
#pragma unroll
        for (int j = 0; j < 4; j++)
#pragma unroll
            for (int r = 0; r < 4; r++) acc[i][j][r] = 0.0f;

    const int nk = K / 64;

    auto load_stage = [&](int stage, int k0) {
        const __half* ah;
        int lda, kk;
        if (k0 < Ks) { ah = a0h; lda = Ks;     kk = k0; }
        else         { ah = a1h; lda = K - Ks; kk = k0 - Ks; }
        const uint32_t stb = sbase + (uint32_t)stage * STAGE_ELEMS * 2;
#pragma unroll
        for (int r = 0; r < 4; r++) {
            const int c   = tid + r * 256;        // 0..1023
            const int row = c >> 3;
            const int seg = c & 7;
            const uint32_t so = stb + (uint32_t)(row * SSTR + seg * 8) * 2;
            CP_ASYNC16(so + OFF_A * 2, ah  + (size_t)(bm + row) * lda + kk + seg * 8);
            CP_ASYNC16(so + OFF_B * 2, bhp + (size_t)(bn + row) * K   + k0 + seg * 8);
        }
        CP_COMMIT();
    };

    const int lrow = (lane & 7) + ((lane >> 3) & 1) * 8;   // 0..15
    const int lcol = (lane >> 4) * 8;                      // 0 or 8
    uint32_t aoff[4], boff[2];
#pragma unroll
    for (int i = 0; i < 4; i++)
        aoff[i] = (uint32_t)(((wm + i * 16 + lrow) * SSTR + lcol) * 2) + OFF_A * 2;
#pragma unroll
    for (int p = 0; p < 2; p++)
        boff[p] = (uint32_t)(((wn + p * 16 + lrow) * SSTR + lcol) * 2) + OFF_B * 2;

    load_stage(0, 0);
    if (nk > 1) load_stage(1, 64);

    int st_comp = 0;
    int st_load = 2;

    for (int kc = 0; kc < nk; kc++) {
        if (kc + 1 < nk) asm volatile("cp.async.wait_group 1;\n" ::: "memory");
        else             asm volatile("cp.async.wait_group 0;\n" ::: "memory");
        __syncthreads();

        if (kc + 2 < nk) load_stage(st_load, (kc + 2) * 64);

        const uint32_t stb = sbase + (uint32_t)st_comp * STAGE_ELEMS * 2;
        uint32_t ba[4], bb[2];
#pragma unroll
        for (int i = 0; i < 4; i++) ba[i] = stb + aoff[i];
#pragma unroll
        for (int p = 0; p < 2; p++) bb[p] = stb + boff[p];

#pragma unroll
        for (int ks = 0; ks < 4; ks++) {
            uint32_t ah[4][4];
#pragma unroll
            for (int i = 0; i < 4; i++)
                LDSM_X4(ah[i][0], ah[i][1], ah[i][2], ah[i][3], ba[i] + ks * 32);
#pragma unroll
            for (int p = 0; p < 2; p++) {
                uint32_t b0, b1, b2, b3;
                LDSM_X4(b0, b1, b2, b3, bb[p] + ks * 32);
                const int j0 = 2 * p, j1 = 2 * p + 1;
#pragma unroll
                for (int i = 0; i < 4; i++) {
                    float* c0 = acc[i][j0];
                    float* c1 = acc[i][j1];
                    MMA_F16(c0[0], c0[1], c0[2], c0[3],
                            ah[i][0], ah[i][1], ah[i][2], ah[i][3], b0, b2);
                    MMA_F16(c1[0], c1[1], c1[2], c1[3],
                            ah[i][0], ah[i][1], ah[i][2], ah[i][3], b1, b3);
                }
            }
        }
        st_comp = (st_comp == NSTAGE - 1) ? 0 : st_comp + 1;
        st_load = (st_load == NSTAGE - 1) ? 0 : st_load + 1;
    }

    // ---- epilogue ----
    const int tr = lane >> 2;
    const int tc = (lane & 3) * 2;
#pragma unroll
    for (int i = 0; i < 4; i++) {
        const int r0 = bm + wm + i * 16 + tr;
        const int r1 = r0 + 8;
#pragma unroll
        for (int j = 0; j < 4; j++) {
            const int col = bn + wn + j * 8 + tc;
            const float b0 = bias[col], b1 = bias[col + 1];
            float v[4] = {acc[i][j][0] + b0, acc[i][j][1] + b1,
                          acc[i][j][2] + b0, acc[i][j][3] + b1};
#pragma unroll
            for (int r = 0; r < 4; r++) {
                if (ACT == 1)      v[r] = 0.5f * v[r] * (1.0f + erff(v[r] * 0.70710678118654752f));
                else if (ACT == 2) v[r] = 1.0f / (1.0f + expf(-v[r]));
            }
            if (OUTMODE != 2) {
                *(float2*)(C + (size_t)r0 * N + col) = make_float2(v[0], v[1]);
                *(float2*)(C + (size_t)r1 * N + col) = make_float2(v[2], v[3]);
            }
            if (OUTMODE != 0) {
                *(__half2*)(ohi + (size_t)r0 * N + col) = __floats2half2_rn(v[0], v[1]);
                *(__half2*)(ohi + (size_t)r1 * N + col) = __floats2half2_rn(v[2], v[3]);
            }
        }
    }
}

// single-problem GEMM
template<int ACT, int OUTMODE>
__global__ void __launch_bounds__(256, 2)
gemm_mma(const __half* __restrict__ a0h, const __half* __restrict__ a1h, int Ks,
         const __half* __restrict__ bhp,
         const float* __restrict__ bias, float* __restrict__ C,
         __half* __restrict__ ohi,
         int M, int N, int K)
{
    gemm_body<ACT, OUTMODE>(a0h, a1h, Ks, bhp, bias, C, ohi, M, N, K,
                            blockIdx.y * 128, blockIdx.x * 128);
}

// dual-problem GEMM (z selects): both ACT=0, fp16-only out
__global__ void __launch_bounds__(256, 2)
gemm_mma_dual(const __half* __restrict__ aA, const __half* __restrict__ wA,
              const float* __restrict__ biasA, __half* __restrict__ outA, int KA,
              const __half* __restrict__ aB, const __half* __restrict__ wB,
              const float* __restrict__ biasB, __half* __restrict__ outB, int KB,
              int M, int N)
{
    const __half* a  = blockIdx.z ? aB   : aA;
    const __half* w  = blockIdx.z ? wB   : wA;
    const float* bi  = blockIdx.z ? biasB : biasA;
    __half* o        = blockIdx.z ? outB : outA;
    const int K      = blockIdx.z ? KB   : KA;
    gemm_body<0, 2>(a, a, K, w, bi, nullptr, o, M, N, K,
                    blockIdx.y * 128, blockIdx.x * 128);
}

// ---------------------------------------------------------------------------
// fused fp32 -> fp16 conversion over 6 buffers (sizes in float4 units).
// 2 independent float4s per thread (MLP=2), single 8B store per float4.
// ---------------------------------------------------------------------------
__device__ __forceinline__ void cvt_one(
    int t,
    const float* __restrict__ i0, __half* __restrict__ o0, int n0,
    const float* __restrict__ i1, __half* __restrict__ o1, int n1,
    const float* __restrict__ i2, __half* __restrict__ o2, int n2,
    const float* __restrict__ i3, __half* __restrict__ o3, int n3,
    const float* __restrict__ i4, __half* __restrict__ o4, int n4,
    const float* __restrict__ i5, __half* __restrict__ o5, int n5)
{
    const float* in; __half* out;
    if      (t < n0)                { in = i0; out = o0; }
    else if (t < n0+n1)             { t -= n0;             in = i1; out = o1; }
    else if (t < n0+n1+n2)          { t -= n0+n1;          in = i2; out = o2; }
    else if (t < n0+n1+n2+n3)       { t -= n0+n1+n2;       in = i3; out = o3; }
    else if (t < n0+n1+n2+n3+n4)    { t -= n0+n1+n2+n3;    in = i4; out = o4; }
    else if (t < n0+n1+n2+n3+n4+n5) { t -= n0+n1+n2+n3+n4; in = i5; out = o5; }
    else return;
    float4 v = ((const float4*)in)[t];
    __half2 lo = __floats2half2_rn(v.x, v.y);
    __half2 hi = __floats2half2_rn(v.z, v.w);
    uint2 u;
    u.x = *(const uint32_t*)&lo;
    u.y = *(const uint32_t*)&hi;
    ((uint2*)out)[t] = u;
}

__global__ void __launch_bounds__(256)
cvt6_kernel(const float* __restrict__ i0, __half* __restrict__ o0, int n0,
            const float* __restrict__ i1, __half* __restrict__ o1, int n1,
            const float* __restrict__ i2, __half* __restrict__ o2, int n2,
            const float* __restrict__ i3, __half* __restrict__ o3, int n3,
            const float* __restrict__ i4, __half* __restrict__ o4, int n4,
            const float* __restrict__ i5, __half* __restrict__ o5, int n5)
{
    const int base = blockIdx.x * 512 + threadIdx.x;
    cvt_one(base,       i0,o0,n0, i1,o1,n1, i2,o2,n2, i3,o3,n3, i4,o4,n4, i5,o5,n5);
    cvt_one(base + 256, i0,o0,n0, i1,o1,n1, i2,o2,n2, i3,o3,n3, i4,o4,n4, i5,o5,n5);
}

// ---------------------------------------------------------------------------
// 4-key attention; reads h/x_proj/q fp16; writes attn fp16.
// ---------------------------------------------------------------------------
__global__ void __launch_bounds__(256)
attn_kernel(const __half* __restrict__ h_prev, const __half* __restrict__ xproj,
            const __half* __restrict__ q, __half* __restrict__ ah)
{
    const int gw   = (blockIdx.x * 256 + threadIdx.x) >> 5;
    const int lane = threadIdx.x & 31;
    if (gw >= B_ * NH_) return;
    const size_t base = (size_t)(gw / NH_) * H_ + (size_t)(gw % NH_) * HD_ + lane * 16;

    const uint4* hp = (const uint4*)(h_prev + base);
    const uint4* xp = (const uint4*)(xproj + base);
    const uint4* qp = (const uint4*)(q + base);

    float hf[16], xf[16], qf[16];
#pragma unroll
    for (int k = 0; k < 2; k++) {
        uint4 uh = hp[k];
        uint4 ux = xp[k];
        uint4 uq = qp[k];
        const __half2* ph = (const __half2*)&uh;
        const __half2* px = (const __half2*)&ux;
        const __half2* pq = (const __half2*)&uq;
#pragma unroll
        for (int m = 0; m < 4; m++) {
            float2 th = __half22float2(ph[m]);
            float2 tx = __half22float2(px[m]);
            float2 tq = __half22float2(pq[m]);
            hf[8*k + 2*m] = th.x; hf[8*k + 2*m + 1] = th.y;
            xf[8*k + 2*m] = tx.x; xf[8*k + 2*m + 1] = tx.y;
            qf[8*k + 2*m] = tq.x; qf[8*k + 2*m + 1] = tq.y;
        }
    }

    float s0 = 0.f, s1 = 0.f, s3 = 0.f;
#pragma unroll
    for (int k = 0; k < 16; k++) {
        s0 += qf[k] * hf[k];
        s1 += qf[k] * xf[k];
        s3 += qf[k] * hf[k] * xf[k];
    }
#pragma unroll
    for (int off = 16; off > 0; off >>= 1) {
        s0 += __shfl_xor_sync(0xffffffffu, s0, off);
        s1 += __shfl_xor_sync(0xffffffffu, s1, off);
        s3 += __shfl_xor_sync(0xffffffffu, s3, off);
    }
    const float inv = rsqrtf((float)HD_);
    float sc0 = s0 * inv, sc1 = s1 * inv, sc2 = (s0 + s1) * inv, sc3 = s3 * inv;
    float m  = fmaxf(fmaxf(sc0, sc1), fmaxf(sc2, sc3));
    float e0 = expf(sc0 - m), e1 = expf(sc1 - m), e2 = expf(sc2 - m), e3 = expf(sc3 - m);
    float rs = 1.0f / (e0 + e1 + e2 + e3);
    float w0 = e0 * rs, w1 = e1 * rs, w2 = e2 * rs, w3 = e3 * rs;
    float ch = w0 + w2, cx = w1 + w2;

    __half2 oh[8];
#pragma unroll
    for (int k = 0; k < 8; k++) {
        float o0 = ch * hf[2*k]   + cx * xf[2*k]   + w3 * hf[2*k]   * xf[2*k];
        float o1 = ch * hf[2*k+1] + cx * xf[2*k+1] + w3 * hf[2*k+1] * xf[2*k+1];
        oh[k] = __floats2half2_rn(o0, o1);
    }
    uint4* op = (uint4*)(ah + base);
    op[0] = *(uint4*)&oh[0];
    op[1] = *(uint4*)&oh[4];
}

// ---------------------------------------------------------------------------
// LayerNorm + gated mix (attn_gelu fp16, gate fp16, h fp32)
// ---------------------------------------------------------------------------
__global__ void __launch_bounds__(256)
ln_gate_kernel(const __half* __restrict__ attn_g, const float* __restrict__ h_prev,
               const __half* __restrict__ gate, const float* __restrict__ gamma,
               const float* __restrict__ beta, float* __restrict__ out)
{
    const int b   = blockIdx.x;
    const int tid = threadIdx.x;
    const size_t rb = (size_t)b * H_;

    float4 y[2], h4[2];
    float sum = 0.f, sq = 0.f;
#pragma unroll
    for (int c = 0; c < 2; c++) {
        int d = c * 1024 + tid * 4;
        const __half2* ap = (const __half2*)(attn_g + rb + d);
        float2 a01 = __half22float2(ap[0]);
        float2 a23 = __half22float2(ap[1]);
        float4 hh = *(const float4*)(h_prev + rb + d);
        float4 yy = make_float4(a01.x + hh.x, a01.y + hh.y, a23.x + hh.z, a23.y + hh.w);
        y[c] = yy; h4[c] = hh;
        sum += yy.x + yy.y + yy.z + yy.w;
        sq  += yy.x * yy.x + yy.y * yy.y + yy.z * yy.z + yy.w * yy.w;
    }
#pragma unroll
    for (int off = 16; off > 0; off >>= 1) {
        sum += __shfl_xor_sync(0xffffffffu, sum, off);
        sq  += __shfl_xor_sync(0xffffffffu, sq,  off);
    }
    __shared__ float s_sum[8], s_sq[8];
    __shared__ float s_mu, s_rstd;
    if ((tid & 31) == 0) { s_sum[tid >> 5] = sum; s_sq[tid >> 5] = sq; }
    __syncthreads();
    if (tid == 0) {
        float S = 0.f, Q = 0.f;
#pragma unroll
        for (int i = 0; i < 8; i++) { S += s_sum[i]; Q += s_sq[i]; }
        float mu  = S / (float)H_;
        float var = Q / (float)H_ - mu * mu;
        s_mu = mu;
        s_rstd = rsqrtf(var + EPS_);
    }
    __syncthreads();
    const float mu = s_mu, rstd = s_rstd;

#pragma unroll
    for (int c = 0; c < 2; c++) {
        int d = c * 1024 + tid * 4;
        const __half2* gp = (const __half2*)(gate + rb + d);
        float2 g01 = __half22float2(gp[0]);
        float2 g23 = __half22float2(gp[1]);
        float4 gm = *(const float4*)(gamma + d);
        float4 bt = *(const float4*)(beta  + d);
        float4 yy = y[c], hh = h4[c], o;
        float c0 = (yy.x - mu) * rstd * gm.x + bt.x;
        float c1 = (yy.y - mu) * rstd * gm.y + bt.y;
        float c2 = (yy.z - mu) * rstd * gm.z + bt.z;
        float c3 = (yy.w - mu) * rstd * gm.w + bt.w;
        o.x = g01.x * c0 + (1.0f - g01.x) * hh.x;
        o.y = g01.y * c1 + (1.0f - g01.y) * hh.y;
        o.z = g23.x * c2 + (1.0f - g23.x) * hh.z;
        o.w = g23.y * c3 + (1.0f - g23.y) * hh.w;
        *(float4*)(out + rb + d) = o;
    }
}

// ---------------------------------------------------------------------------
extern "C" void kernel_launch(void* const* d_in, const int* in_sizes, int n_in,
                              void* d_out, int out_size)
{
    const float* h_prev = (const float*)d_in[0];
    const float* x      = (const float*)d_in[1];
    const float* W_proj = (const float*)d_in[2];
    const float* b_proj = (const float*)d_in[3];
    const float* W_q    = (const float*)d_in[4];
    const float* b_q    = (const float*)d_in[5];
    const float* W_o    = (const float*)d_in[6];
    const float* b_o    = (const float*)d_in[7];
    const float* W_g    = (const float*)d_in[8];
    const float* b_g    = (const float*)d_in[9];
    const float* gamma  = (const float*)d_in[10];
    const float* beta   = (const float*)d_in[11];
    float* out = (float*)d_out;

    __half *xsh, *hsh, *xph, *qh, *ath, *agh;
    __half *wph, *wqh, *woh, *wgh;
    cudaGetSymbolAddress((void**)&xsh, g_xs_h);
    cudaGetSymbolAddress((void**)&hsh, g_hs_h);
    cudaGetSymbolAddress((void**)&xph, g_xp_h);
    cudaGetSymbolAddress((void**)&qh,  g_q_h);
    cudaGetSymbolAddress((void**)&ath, g_at_h);
    cudaGetSymbolAddress((void**)&agh, g_ag_h);
    cudaGetSymbolAddress((void**)&wph, g_wp_h);
    cudaGetSymbolAddress((void**)&wqh, g_wq_h);
    cudaGetSymbolAddress((void**)&woh, g_wo_h);
    cudaGetSymbolAddress((void**)&wgh, g_wg_h);

    cudaFuncSetAttribute(gemm_mma_dual,  cudaFuncAttributeMaxDynamicSharedMemorySize, SMEM_BYTES);
    cudaFuncSetAttribute(gemm_mma<1, 2>, cudaFuncAttributeMaxDynamicSharedMemorySize, SMEM_BYTES);
    cudaFuncSetAttribute(gemm_mma<2, 2>, cudaFuncAttributeMaxDynamicSharedMemorySize, SMEM_BYTES);

    // --- launch #0: ALL conversions fused (weights + activations) ---
    {
        int n0 = H_ * IN_ / 4;       // W_proj
        int n1 = H_ * H_ / 4;        // W_q
        int n2 = H_ * H_ / 4;        // W_o
        int n3 = H_ * 2 * H_ / 4;    // W_g
        int n4 = B_ * IN_ / 4;       // x
        int n5 = B_ * H_ / 4;        // h_prev
        int nt = n0 + n1 + n2 + n3 + n4 + n5;
        cvt6_kernel<<<(nt + 511) / 512, 256>>>(
            W_proj, wph, n0, W_q, wqh, n1, W_o, woh, n2,
            W_g, wgh, n3, x, xsh, n4, h_prev, hsh, n5);
    }

    dim3 grid2(H_ / 128, B_ / 128, 2);   // merged x_proj + q: 2048 CTAs
    dim3 grid(H_ / 128, B_ / 128);       // 1024 CTAs

    // #1) merged: z=0 -> x_proj (K=1024), z=1 -> q (K=2048)
    gemm_mma_dual<<<grid2, 256, SMEM_BYTES>>>(
        xsh, wph, b_proj, xph, IN_,
        hsh, wqh, b_q,    qh,  H_,
        B_, H_);
    // #2) attention -> attn fp16 (all-fp16 reads)
    attn_kernel<<<(B_ * NH_) / 8, 256>>>(hsh, xph, qh, ath);
    // #3) attn_gelu (fp16 only)
    gemm_mma<1, 2><<<grid, 256, SMEM_BYTES>>>(
        ath, ath, H_, woh, b_o, nullptr, agh, B_, H_, H_);
    // #4) gate (fp16 only, reuses q buffer)
    gemm_mma<2, 2><<<grid, 256, SMEM_BYTES>>>(
        hsh, agh, H_, wgh, b_g, nullptr, qh, B_, H_, 2 * H_);
    // #5) layernorm + gated mix (ag fp16, gate fp16, h fp32)
    ln_gate_kernel<<<B_, 256>>>(agh, h_prev, qh, gamma, beta, out);
}

// round 15
// speedup vs baseline: 1.5288x; 1.5288x over previous
#include <cuda_runtime.h>
#include <cuda_fp16.h>
#include <math.h>
#include <stdint.h>

#define B_  8192
#define IN_ 1024
#define H_  2048
#define NH_ 4
#define HD_ 512
#define EPS_ 1e-5f

// ---------------------------------------------------------------------------
// Device scratch (allocation-free rule)
// ---------------------------------------------------------------------------
// fp16 activations / intermediates
__device__ __align__(128) __half g_xs_h[(size_t)B_ * IN_];   // x fp16
__device__ __align__(128) __half g_hs_h[(size_t)B_ * H_];    // h_prev fp16
__device__ __align__(128) __half g_xp_h[(size_t)B_ * H_];    // x_proj fp16
__device__ __align__(128) __half g_q_h [(size_t)B_ * H_];    // q fp16 -> gate fp16
__device__ __align__(128) __half g_at_h[(size_t)B_ * H_];    // attn fp16
__device__ __align__(128) __half g_ag_h[(size_t)B_ * H_];    // attn_gelu fp16

// fp16 weights
__device__ __align__(128) __half g_wp_h[(size_t)H_ * IN_];
__device__ __align__(128) __half g_wq_h[(size_t)H_ * H_];
__device__ __align__(128) __half g_wo_h[(size_t)H_ * H_];
__device__ __align__(128) __half g_wg_h[(size_t)H_ * 2 * H_];

// ---------------------------------------------------------------------------
// PTX helpers (base-target-safe)
// ---------------------------------------------------------------------------
__device__ __forceinline__ uint32_t smem_u32(const void* p) {
    uint32_t a;
    asm("{ .reg .u64 t; cvta.to.shared.u64 t, %1; cvt.u32.u64 %0, t; }" : "=r"(a) : "l"(p));
    return a;
}

#define CP_ASYNC16(sa, ga) \
    asm volatile("cp.async.cg.shared.global [%0], [%1], 16;\n" :: "r"(sa), "l"(ga))
#define CP_COMMIT()  asm volatile("cp.async.commit_group;\n" ::: "memory")

#define LDSM_X4(r0, r1, r2, r3, addr) \
    asm volatile("ldmatrix.sync.aligned.m8n8.x4.shared.b16 {%0,%1,%2,%3}, [%4];" \
        : "=r"(r0), "=r"(r1), "=r"(r2), "=r"(r3) : "r"(addr))

#define MMA_F16(c0, c1, c2, c3, a0, a1, a2, a3, b0, b1) \
    asm volatile("mma.sync.aligned.m16n8k16.row.col.f32.f16.f16.f32 " \
        "{%0,%1,%2,%3}, {%4,%5,%6,%7}, {%8,%9}, {%0,%1,%2,%3};" \
        : "+f"(c0), "+f"(c1), "+f"(c2), "+f"(c3) \
        : "r"(a0), "r"(a1), "r"(a2), "r"(a3), "r"(b0), "r"(b1))

// ---------------------------------------------------------------------------
// SMEM: per stage: A 128x64 fp16, B 128x64 fp16, row stride 72 elems (144B).
// 3 stages = 108 KB -> 2 CTA/SM.
// ---------------------------------------------------------------------------
#define SSTR 72
#define T_ELEMS (128 * SSTR)               // 9216
#define OFF_A 0
#define OFF_B T_ELEMS
#define STAGE_ELEMS (2 * T_ELEMS)          // 18432
#define NSTAGE 3
#define SMEM_BYTES (NSTAGE * STAGE_ELEMS * 2)   // 110592

// ---------------------------------------------------------------------------
// GEMM body: CTA 128x128, 8 warps (warp tile 64x32), K-chunk 64, 3 stages.
// ---------------------------------------------------------------------------
template<int ACT, int OUTMODE>   // OUTMODE: 0 fp32, 1 both, 2 fp16
__device__ __forceinline__ void gemm_body(
    const __half* __restrict__ a0h, const __half* __restrict__ a1h, int Ks,
    const __half* __restrict__ bhp,
    const float* __restrict__ bias, float* __restrict__ C,
    __half* __restrict__ ohi,
    int M, int N, int K, int bm, int bn)
{
    extern __shared__ __align__(128) char smem[];
    const uint32_t sbase = smem_u32(smem);
    const int tid  = threadIdx.x;
    const int warp = tid >> 5;
    const int lane = tid & 31;
    const int wm = (warp >> 2) * 64;       // 0 or 64
    const int wn = (warp & 3) * 32;        // 0..96

    float acc[4][4][4];
#pragma unroll
    for (int i = 0; i < 4; i++)
#pragma unroll
        for (int j = 0; j < 4; j++)
#pragma unroll
            for (int r = 0; r < 4; r++) acc[i][j][r] = 0.0f;

    const int nk = K / 64;

    auto load_stage = [&](int stage, int k0) {
        const __half* ah;
        int lda, kk;
        if (k0 < Ks) { ah = a0h; lda = Ks;     kk = k0; }
        else         { ah = a1h; lda = K - Ks; kk = k0 - Ks; }
        const uint32_t stb = sbase + (uint32_t)stage * STAGE_ELEMS * 2;
#pragma unroll
        for (int r = 0; r < 4; r++) {
            const int c   = tid + r * 256;        // 0..1023
            const int row = c >> 3;
            const int seg = c & 7;
            const uint32_t so = stb + (uint32_t)(row * SSTR + seg * 8) * 2;
            CP_ASYNC16(so + OFF_A * 2, ah  + (size_t)(bm + row) * lda + kk + seg * 8);
            CP_ASYNC16(so + OFF_B * 2, bhp + (size_t)(bn + row) * K   + k0 + seg * 8);
        }
        CP_COMMIT();
    };

    const int lrow = (lane & 7) + ((lane >> 3) & 1) * 8;   // 0..15
    const int lcol = (lane >> 4) * 8;                      // 0 or 8
    uint32_t aoff[4], boff[2];
#pragma unroll
    for (int i = 0; i < 4; i++)
        aoff[i] = (uint32_t)(((wm + i * 16 + lrow) * SSTR + lcol) * 2) + OFF_A * 2;
#pragma unroll
    for (int p = 0; p < 2; p++)
        boff[p] = (uint32_t)(((wn + p * 16 + lrow) * SSTR + lcol) * 2) + OFF_B * 2;

    load_stage(0, 0);
    if (nk > 1) load_stage(1, 64);

    int st_comp = 0;
    int st_load = 2;

    for (int kc = 0; kc < nk; kc++) {
        if (kc + 1 < nk) asm volatile("cp.async.wait_group 1;\n" ::: "memory");
        else             asm volatile("cp.async.wait_group 0;\n" ::: "memory");
        __syncthreads();

        if (kc + 2 < nk) load_stage(st_load, (kc + 2) * 64);

        const uint32_t stb = sbase + (uint32_t)st_comp * STAGE_ELEMS * 2;
        uint32_t ba[4], bb[2];
#pragma unroll
        for (int i = 0; i < 4; i++) ba[i] = stb + aoff[i];
#pragma unroll
        for (int p = 0; p < 2; p++) bb[p] = stb + boff[p];

#pragma unroll
        for (int ks = 0; ks < 4; ks++) {
            uint32_t ah[4][4];
#pragma unroll
            for (int i = 0; i < 4; i++)
                LDSM_X4(ah[i][0], ah[i][1], ah[i][2], ah[i][3], ba[i] + ks * 32);
#pragma unroll
            for (int p = 0; p < 2; p++) {
                uint32_t b0, b1, b2, b3;
                LDSM_X4(b0, b1, b2, b3, bb[p] + ks * 32);
                const int j0 = 2 * p, j1 = 2 * p + 1;
#pragma unroll
                for (int i = 0; i < 4; i++) {
                    float* c0 = acc[i][j0];
                    float* c1 = acc[i][j1];
                    MMA_F16(c0[0], c0[1], c0[2], c0[3],
                            ah[i][0], ah[i][1], ah[i][2], ah[i][3], b0, b2);
                    MMA_F16(c1[0], c1[1], c1[2], c1[3],
                            ah[i][0], ah[i][1], ah[i][2], ah[i][3], b1, b3);
                }
            }
        }
        st_comp = (st_comp == NSTAGE - 1) ? 0 : st_comp + 1;
        st_load = (st_load == NSTAGE - 1) ? 0 : st_load + 1;
    }

    // ---- epilogue ----
    const int tr = lane >> 2;
    const int tc = (lane & 3) * 2;
#pragma unroll
    for (int i = 0; i < 4; i++) {
        const int r0 = bm + wm + i * 16 + tr;
        const int r1 = r0 + 8;
#pragma unroll
        for (int j = 0; j < 4; j++) {
            const int col = bn + wn + j * 8 + tc;
            const float b0 = bias[col], b1 = bias[col + 1];
            float v[4] = {acc[i][j][0] + b0, acc[i][j][1] + b1,
                          acc[i][j][2] + b0, acc[i][j][3] + b1};
#pragma unroll
            for (int r = 0; r < 4; r++) {
                if (ACT == 1)      v[r] = 0.5f * v[r] * (1.0f + erff(v[r] * 0.70710678118654752f));
                else if (ACT == 2) v[r] = 1.0f / (1.0f + expf(-v[r]));
            }
            if (OUTMODE != 2) {
                *(float2*)(C + (size_t)r0 * N + col) = make_float2(v[0], v[1]);
                *(float2*)(C + (size_t)r1 * N + col) = make_float2(v[2], v[3]);
            }
            if (OUTMODE != 0) {
                *(__half2*)(ohi + (size_t)r0 * N + col) = __floats2half2_rn(v[0], v[1]);
                *(__half2*)(ohi + (size_t)r1 * N + col) = __floats2half2_rn(v[2], v[3]);
            }
        }
    }
}

// single-problem GEMM
template<int ACT, int OUTMODE>
__global__ void __launch_bounds__(256, 2)
gemm_mma(const __half* __restrict__ a0h, const __half* __restrict__ a1h, int Ks,
         const __half* __restrict__ bhp,
         const float* __restrict__ bias, float* __restrict__ C,
         __half* __restrict__ ohi,
         int M, int N, int K)
{
    gemm_body<ACT, OUTMODE>(a0h, a1h, Ks, bhp, bias, C, ohi, M, N, K,
                            blockIdx.y * 128, blockIdx.x * 128);
}

// dual-problem GEMM (z selects): both ACT=0, fp16-only out
__global__ void __launch_bounds__(256, 2)
gemm_mma_dual(const __half* __restrict__ aA, const __half* __restrict__ wA,
              const float* __restrict__ biasA, __half* __restrict__ outA, int KA,
              const __half* __restrict__ aB, const __half* __restrict__ wB,
              const float* __restrict__ biasB, __half* __restrict__ outB, int KB,
              int M, int N)
{
    const __half* a  = blockIdx.z ? aB   : aA;
    const __half* w  = blockIdx.z ? wB   : wA;
    const float* bi  = blockIdx.z ? biasB : biasA;
    __half* o        = blockIdx.z ? outB : outA;
    const int K      = blockIdx.z ? KB   : KA;
    gemm_body<0, 2>(a, a, K, w, bi, nullptr, o, M, N, K,
                    blockIdx.y * 128, blockIdx.x * 128);
}

// ---------------------------------------------------------------------------
// single fused fp32 -> fp16 conversion over 6 buffers (sizes in float4 units)
// ---------------------------------------------------------------------------
__global__ void __launch_bounds__(256)
cvt6_kernel(const float* __restrict__ i0, __half* __restrict__ o0, int n0,
            const float* __restrict__ i1, __half* __restrict__ o1, int n1,
            const float* __restrict__ i2, __half* __restrict__ o2, int n2,
            const float* __restrict__ i3, __half* __restrict__ o3, int n3,
            const float* __restrict__ i4, __half* __restrict__ o4, int n4,
            const float* __restrict__ i5, __half* __restrict__ o5, int n5)
{
    int t = blockIdx.x * 256 + threadIdx.x;
    const float* in; __half* out;
    if      (t < n0)                          { in = i0; out = o0; }
    else if (t < n0+n1)                       { t -= n0;             in = i1; out = o1; }
    else if (t < n0+n1+n2)                    { t -= n0+n1;          in = i2; out = o2; }
    else if (t < n0+n1+n2+n3)                 { t -= n0+n1+n2;       in = i3; out = o3; }
    else if (t < n0+n1+n2+n3+n4)              { t -= n0+n1+n2+n3;    in = i4; out = o4; }
    else if (t < n0+n1+n2+n3+n4+n5)           { t -= n0+n1+n2+n3+n4; in = i5; out = o5; }
    else return;
    float4 v = ((const float4*)in)[t];
    ((__half2*)out)[2 * t]     = __floats2half2_rn(v.x, v.y);
    ((__half2*)out)[2 * t + 1] = __floats2half2_rn(v.z, v.w);
}

// ---------------------------------------------------------------------------
// 4-key attention; reads h/x_proj/q fp16; writes attn fp16.
// One warp per (b, head); each lane owns 16 contiguous dims.
// ---------------------------------------------------------------------------
__global__ void __launch_bounds__(256)
attn_kernel(const __half* __restrict__ h_prev, const __half* __restrict__ xproj,
            const __half* __restrict__ q, __half* __restrict__ ah)
{
    const int gw   = (blockIdx.x * 256 + threadIdx.x) >> 5;
    const int lane = threadIdx.x & 31;
    if (gw >= B_ * NH_) return;
    const size_t base = (size_t)(gw / NH_) * H_ + (size_t)(gw % NH_) * HD_ + lane * 16;

    const uint4* hp = (const uint4*)(h_prev + base);
    const uint4* xp = (const uint4*)(xproj + base);
    const uint4* qp = (const uint4*)(q + base);

    float hf[16], xf[16], qf[16];
#pragma unroll
    for (int k = 0; k < 2; k++) {
        uint4 uh = hp[k];
        uint4 ux = xp[k];
        uint4 uq = qp[k];
        const __half2* ph = (const __half2*)&uh;
        const __half2* px = (const __half2*)&ux;
        const __half2* pq = (const __half2*)&uq;
#pragma unroll
        for (int m = 0; m < 4; m++) {
            float2 th = __half22float2(ph[m]);
            float2 tx = __half22float2(px[m]);
            float2 tq = __half22float2(pq[m]);
            hf[8*k + 2*m] = th.x; hf[8*k + 2*m + 1] = th.y;
            xf[8*k + 2*m] = tx.x; xf[8*k + 2*m + 1] = tx.y;
            qf[8*k + 2*m] = tq.x; qf[8*k + 2*m + 1] = tq.y;
        }
    }

    float s0 = 0.f, s1 = 0.f, s3 = 0.f;
#pragma unroll
    for (int k = 0; k < 16; k++) {
        s0 += qf[k] * hf[k];
        s1 += qf[k] * xf[k];
        s3 += qf[k] * hf[k] * xf[k];
    }
#pragma unroll
    for (int off = 16; off > 0; off >>= 1) {
        s0 += __shfl_xor_sync(0xffffffffu, s0, off);
        s1 += __shfl_xor_sync(0xffffffffu, s1, off);
        s3 += __shfl_xor_sync(0xffffffffu, s3, off);
    }
    const float inv = rsqrtf((float)HD_);
    float sc0 = s0 * inv, sc1 = s1 * inv, sc2 = (s0 + s1) * inv, sc3 = s3 * inv;
    float m  = fmaxf(fmaxf(sc0, sc1), fmaxf(sc2, sc3));
    float e0 = expf(sc0 - m), e1 = expf(sc1 - m), e2 = expf(sc2 - m), e3 = expf(sc3 - m);
    float rs = 1.0f / (e0 + e1 + e2 + e3);
    float w0 = e0 * rs, w1 = e1 * rs, w2 = e2 * rs, w3 = e3 * rs;
    float ch = w0 + w2, cx = w1 + w2;

    __half2 oh[8];
#pragma unroll
    for (int k = 0; k < 8; k++) {
        float o0 = ch * hf[2*k]   + cx * xf[2*k]   + w3 * hf[2*k]   * xf[2*k];
        float o1 = ch * hf[2*k+1] + cx * xf[2*k+1] + w3 * hf[2*k+1] * xf[2*k+1];
        oh[k] = __floats2half2_rn(o0, o1);
    }
    uint4* op = (uint4*)(ah + base);
    op[0] = *(uint4*)&oh[0];
    op[1] = *(uint4*)&oh[4];
}

// ---------------------------------------------------------------------------
// LayerNorm + gated mix (attn_gelu fp16, gate fp16, h fp32)
// ---------------------------------------------------------------------------
__global__ void __launch_bounds__(256)
ln_gate_kernel(const __half* __restrict__ attn_g, const float* __restrict__ h_prev,
               const __half* __restrict__ gate, const float* __restrict__ gamma,
               const float* __restrict__ beta, float* __restrict__ out)
{
    const int b   = blockIdx.x;
    const int tid = threadIdx.x;
    const size_t rb = (size_t)b * H_;

    float4 y[2], h4[2];
    float sum = 0.f, sq = 0.f;
#pragma unroll
    for (int c = 0; c < 2; c++) {
        int d = c * 1024 + tid * 4;
        const __half2* ap = (const __half2*)(attn_g + rb + d);
        float2 a01 = __half22float2(ap[0]);
        float2 a23 = __half22float2(ap[1]);
        float4 hh = *(const float4*)(h_prev + rb + d);
        float4 yy = make_float4(a01.x + hh.x, a01.y + hh.y, a23.x + hh.z, a23.y + hh.w);
        y[c] = yy; h4[c] = hh;
        sum += yy.x + yy.y + yy.z + yy.w;
        sq  += yy.x * yy.x + yy.y * yy.y + yy.z * yy.z + yy.w * yy.w;
    }
#pragma unroll
    for (int off = 16; off > 0; off >>= 1) {
        sum += __shfl_xor_sync(0xffffffffu, sum, off);
        sq  += __shfl_xor_sync(0xffffffffu, sq,  off);
    }
    __shared__ float s_sum[8], s_sq[8];
    __shared__ float s_mu, s_rstd;
    if ((tid & 31) == 0) { s_sum[tid >> 5] = sum; s_sq[tid >> 5] = sq; }
    __syncthreads();
    if (tid == 0) {
        float S = 0.f, Q = 0.f;
#pragma unroll
        for (int i = 0; i < 8; i++) { S += s_sum[i]; Q += s_sq[i]; }
        float mu  = S / (float)H_;
        float var = Q / (float)H_ - mu * mu;
        s_mu = mu;
        s_rstd = rsqrtf(var + EPS_);
    }
    __syncthreads();
    const float mu = s_mu, rstd = s_rstd;

#pragma unroll
    for (int c = 0; c < 2; c++) {
        int d = c * 1024 + tid * 4;
        const __half2* gp = (const __half2*)(gate + rb + d);
        float2 g01 = __half22float2(gp[0]);
        float2 g23 = __half22float2(gp[1]);
        float4 gm = *(const float4*)(gamma + d);
        float4 bt = *(const float4*)(beta  + d);
        float4 yy = y[c], hh = h4[c], o;
        float c0 = (yy.x - mu) * rstd * gm.x + bt.x;
        float c1 = (yy.y - mu) * rstd * gm.y + bt.y;
        float c2 = (yy.z - mu) * rstd * gm.z + bt.z;
        float c3 = (yy.w - mu) * rstd * gm.w + bt.w;
        o.x = g01.x * c0 + (1.0f - g01.x) * hh.x;
        o.y = g01.y * c1 + (1.0f - g01.y) * hh.y;
        o.z = g23.x * c2 + (1.0f - g23.x) * hh.z;
        o.w = g23.y * c3 + (1.0f - g23.y) * hh.w;
        *(float4*)(out + rb + d) = o;
    }
}

// ---------------------------------------------------------------------------
extern "C" void kernel_launch(void* const* d_in, const int* in_sizes, int n_in,
                              void* d_out, int out_size)
{
    const float* h_prev = (const float*)d_in[0];
    const float* x      = (const float*)d_in[1];
    const float* W_proj = (const float*)d_in[2];
    const float* b_proj = (const float*)d_in[3];
    const float* W_q    = (const float*)d_in[4];
    const float* b_q    = (const float*)d_in[5];
    const float* W_o    = (const float*)d_in[6];
    const float* b_o    = (const float*)d_in[7];
    const float* W_g    = (const float*)d_in[8];
    const float* b_g    = (const float*)d_in[9];
    const float* gamma  = (const float*)d_in[10];
    const float* beta   = (const float*)d_in[11];
    float* out = (float*)d_out;

    __half *xsh, *hsh, *xph, *qh, *ath, *agh;
    __half *wph, *wqh, *woh, *wgh;
    cudaGetSymbolAddress((void**)&xsh, g_xs_h);
    cudaGetSymbolAddress((void**)&hsh, g_hs_h);
    cudaGetSymbolAddress((void**)&xph, g_xp_h);
    cudaGetSymbolAddress((void**)&qh,  g_q_h);
    cudaGetSymbolAddress((void**)&ath, g_at_h);
    cudaGetSymbolAddress((void**)&agh, g_ag_h);
    cudaGetSymbolAddress((void**)&wph, g_wp_h);
    cudaGetSymbolAddress((void**)&wqh, g_wq_h);
    cudaGetSymbolAddress((void**)&woh, g_wo_h);
    cudaGetSymbolAddress((void**)&wgh, g_wg_h);

    cudaFuncSetAttribute(gemm_mma_dual,  cudaFuncAttributeMaxDynamicSharedMemorySize, SMEM_BYTES);
    cudaFuncSetAttribute(gemm_mma<1, 2>, cudaFuncAttributeMaxDynamicSharedMemorySize, SMEM_BYTES);
    cudaFuncSetAttribute(gemm_mma<2, 2>, cudaFuncAttributeMaxDynamicSharedMemorySize, SMEM_BYTES);

    // --- launch #0: ALL conversions fused (weights + activations) ---
    {
        int n0 = H_ * IN_ / 4;       // W_proj
        int n1 = H_ * H_ / 4;        // W_q
        int n2 = H_ * H_ / 4;        // W_o
        int n3 = H_ * 2 * H_ / 4;    // W_g
        int n4 = B_ * IN_ / 4;       // x
        int n5 = B_ * H_ / 4;        // h_prev
        int nt = n0 + n1 + n2 + n3 + n4 + n5;
        cvt6_kernel<<<(nt + 255) / 256, 256>>>(
            W_proj, wph, n0, W_q, wqh, n1, W_o, woh, n2,
            W_g, wgh, n3, x, xsh, n4, h_prev, hsh, n5);
    }

    dim3 grid2(H_ / 128, B_ / 128, 2);   // merged x_proj + q: 2048 CTAs
    dim3 grid(H_ / 128, B_ / 128);       // 1024 CTAs

    // #1) merged: z=0 -> x_proj (K=1024), z=1 -> q (K=2048)
    gemm_mma_dual<<<grid2, 256, SMEM_BYTES>>>(
        xsh, wph, b_proj, xph, IN_,
        hsh, wqh, b_q,    qh,  H_,
        B_, H_);
    // #2) attention -> attn fp16 (all-fp16 reads)
    attn_kernel<<<(B_ * NH_) / 8, 256>>>(hsh, xph, qh, ath);
    // #3) attn_gelu (fp16 only)
    gemm_mma<1, 2><<<grid, 256, SMEM_BYTES>>>(
        ath, ath, H_, woh, b_o, nullptr, agh, B_, H_, H_);
    // #4) gate (fp16 only, reuses q buffer)
    gemm_mma<2, 2><<<grid, 256, SMEM_BYTES>>>(
        hsh, agh, H_, wgh, b_g, nullptr, qh, B_, H_, 2 * H_);
    // #5) layernorm + gated mix (ag fp16, gate fp16, h fp32)
    ln_gate_kernel<<<B_, 256>>>(agh, h_prev, qh, gamma, beta, out);
}

// round 16
// speedup vs baseline: 1.5562x; 1.0179x over previous
#include <cuda_runtime.h>
#include <cuda_fp16.h>
#include <math.h>
#include <stdint.h>

#define B_  8192
#define IN_ 1024
#define H_  2048
#define NH_ 4
#define HD_ 512
#define EPS_ 1e-5f

// ---------------------------------------------------------------------------
// Device scratch (allocation-free rule)
// ---------------------------------------------------------------------------
// fp16 activations / intermediates
__device__ __align__(128) __half g_xs_h[(size_t)B_ * IN_];   // x fp16
__device__ __align__(128) __half g_hs_h[(size_t)B_ * H_];    // h_prev fp16
__device__ __align__(128) __half g_xp_h[(size_t)B_ * H_];    // x_proj fp16
__device__ __align__(128) __half g_q_h [(size_t)B_ * H_];    // q fp16 -> gate fp16
__device__ __align__(128) __half g_at_h[(size_t)B_ * H_];    // attn fp16
__device__ __align__(128) __half g_ag_h[(size_t)B_ * H_];    // attn_gelu fp16

// fp16 weights
__device__ __align__(128) __half g_wp_h[(size_t)H_ * IN_];
__device__ __align__(128) __half g_wq_h[(size_t)H_ * H_];
__device__ __align__(128) __half g_wo_h[(size_t)H_ * H_];
__device__ __align__(128) __half g_wg_h[(size_t)H_ * 2 * H_];

// ---------------------------------------------------------------------------
// PTX helpers (base-target-safe)
// ---------------------------------------------------------------------------
__device__ __forceinline__ uint32_t smem_u32(const void* p) {
    uint32_t a;
    asm("{ .reg .u64 t; cvta.to.shared.u64 t, %1; cvt.u32.u64 %0, t; }" : "=r"(a) : "l"(p));
    return a;
}

#define CP_ASYNC16(sa, ga) \
    asm volatile("cp.async.cg.shared.global [%0], [%1], 16;\n" :: "r"(sa), "l"(ga))
#define CP_COMMIT()  asm volatile("cp.async.commit_group;\n" ::: "memory")

#define LDSM_X4(r0, r1, r2, r3, addr) \
    asm volatile("ldmatrix.sync.aligned.m8n8.x4.shared.b16 {%0,%1,%2,%3}, [%4];" \
        : "=r"(r0), "=r"(r1), "=r"(r2), "=r"(r3) : "r"(addr))

#define MMA_F16(c0, c1, c2, c3, a0, a1, a2, a3, b0, b1) \
    asm volatile("mma.sync.aligned.m16n8k16.row.col.f32.f16.f16.f32 " \
        "{%0,%1,%2,%3}, {%4,%5,%6,%7}, {%8,%9}, {%0,%1,%2,%3};" \
        : "+f"(c0), "+f"(c1), "+f"(c2), "+f"(c3) \
        : "r"(a0), "r"(a1), "r"(a2), "r"(a3), "r"(b0), "r"(b1))

// fast exact-GELU: Abramowitz-Stegun 7.1.26 erf (|abs err| <= 1.5e-7) + __expf
__device__ __forceinline__ float gelu_fast(float v) {
    float s  = v * 0.70710678118654752f;
    float ax = fabsf(s);
    float t  = __fdividef(1.0f, fmaf(0.3275911f, ax, 1.0f));
    float p  = fmaf(fmaf(fmaf(fmaf(1.061405429f, t, -1.453152027f), t,
                               1.421413741f), t, -0.284496736f), t, 0.254829592f) * t;
    float er = 1.0f - p * __expf(-ax * ax);
    er = copysignf(er, s);
    return 0.5f * v * (1.0f + er);
}
__device__ __forceinline__ float sigmoid_fast(float v) {
    return __fdividef(1.0f, 1.0f + __expf(-v));
}

// ---------------------------------------------------------------------------
// SMEM: per stage: A 128x64 fp16, B 128x64 fp16, row stride 72 elems (144B).
// 3 stages = 108 KB -> 2 CTA/SM.
// ---------------------------------------------------------------------------
#define SSTR 72
#define T_ELEMS (128 * SSTR)               // 9216
#define OFF_A 0
#define OFF_B T_ELEMS
#define STAGE_ELEMS (2 * T_ELEMS)          // 18432
#define NSTAGE 3
#define SMEM_BYTES (NSTAGE * STAGE_ELEMS * 2)   // 110592

// ---------------------------------------------------------------------------
// GEMM body: CTA 128x128, 8 warps (warp tile 64x32), K-chunk 64, 3 stages.
// ---------------------------------------------------------------------------
template<int ACT, int OUTMODE>   // OUTMODE: 0 fp32, 1 both, 2 fp16
__device__ __forceinline__ void gemm_body(
    const __half* __restrict__ a0h, const __half* __restrict__ a1h, int Ks,
    const __half* __restrict__ bhp,
    const float* __restrict__ bias, float* __restrict__ C,
    __half* __restrict__ ohi,
    int M, int N, int K, int bm, int bn)
{
    extern __shared__ __align__(128) char smem[];
    const uint32_t sbase = smem_u32(smem);
    const int tid  = threadIdx.x;
    const int warp = tid >> 5;
    const int lane = tid & 31;
    const int wm = (warp >> 2) * 64;       // 0 or 64
    const int wn = (warp & 3) * 32;        // 0..96

    float acc[4][4][4];
#pragma unroll
    for (int i = 0; i < 4; i++)
#pragma unroll
        for (int j = 0; j < 4; j++)
#pragma unroll
            for (int r = 0; r < 4; r++) acc[i][j][r] = 0.0f;

    const int nk = K / 64;

    auto load_stage = [&](int stage, int k0) {
        const __half* ah;
        int lda, kk;
        if (k0 < Ks) { ah = a0h; lda = Ks;     kk = k0; }
        else         { ah = a1h; lda = K - Ks; kk = k0 - Ks; }
        const uint32_t stb = sbase + (uint32_t)stage * STAGE_ELEMS * 2;
#pragma unroll
        for (int r = 0; r < 4; r++) {
            const int c   = tid + r * 256;        // 0..1023
            const int row = c >> 3;
            const int seg = c & 7;
            const uint32_t so = stb + (uint32_t)(row * SSTR + seg * 8) * 2;
            CP_ASYNC16(so + OFF_A * 2, ah  + (size_t)(bm + row) * lda + kk + seg * 8);
            CP_ASYNC16(so + OFF_B * 2, bhp + (size_t)(bn + row) * K   + k0 + seg * 8);
        }
        CP_COMMIT();
    };

    const int lrow = (lane & 7) + ((lane >> 3) & 1) * 8;   // 0..15
    const int lcol = (lane >> 4) * 8;                      // 0 or 8
    uint32_t aoff[4], boff[2];
#pragma unroll
    for (int i = 0; i < 4; i++)
        aoff[i] = (uint32_t)(((wm + i * 16 + lrow) * SSTR + lcol) * 2) + OFF_A * 2;
#pragma unroll
    for (int p = 0; p < 2; p++)
        boff[p] = (uint32_t)(((wn + p * 16 + lrow) * SSTR + lcol) * 2) + OFF_B * 2;

    load_stage(0, 0);
    if (nk > 1) load_stage(1, 64);

    int st_comp = 0;
    int st_load = 2;

    for (int kc = 0; kc < nk; kc++) {
        if (kc + 1 < nk) asm volatile("cp.async.wait_group 1;\n" ::: "memory");
        else             asm volatile("cp.async.wait_group 0;\n" ::: "memory");
        __syncthreads();

        if (kc + 2 < nk) load_stage(st_load, (kc + 2) * 64);

        const uint32_t stb = sbase + (uint32_t)st_comp * STAGE_ELEMS * 2;
        uint32_t ba[4], bb[2];
#pragma unroll
        for (int i = 0; i < 4; i++) ba[i] = stb + aoff[i];
#pragma unroll
        for (int p = 0; p < 2; p++) bb[p] = stb + boff[p];

#pragma unroll
        for (int ks = 0; ks < 4; ks++) {
            uint32_t ah[4][4];
#pragma unroll
            for (int i = 0; i < 4; i++)
                LDSM_X4(ah[i][0], ah[i][1], ah[i][2], ah[i][3], ba[i] + ks * 32);
#pragma unroll
            for (int p = 0; p < 2; p++) {
                uint32_t b0, b1, b2, b3;
                LDSM_X4(b0, b1, b2, b3, bb[p] + ks * 32);
                const int j0 = 2 * p, j1 = 2 * p + 1;
#pragma unroll
                for (int i = 0; i < 4; i++) {
                    float* c0 = acc[i][j0];
                    float* c1 = acc[i][j1];
                    MMA_F16(c0[0], c0[1], c0[2], c0[3],
                            ah[i][0], ah[i][1], ah[i][2], ah[i][3], b0, b2);
                    MMA_F16(c1[0], c1[1], c1[2], c1[3],
                            ah[i][0], ah[i][1], ah[i][2], ah[i][3], b1, b3);
                }
            }
        }
        st_comp = (st_comp == NSTAGE - 1) ? 0 : st_comp + 1;
        st_load = (st_load == NSTAGE - 1) ? 0 : st_load + 1;
    }

    // ---- epilogue ----
    const int tr = lane >> 2;
    const int tc = (lane & 3) * 2;
#pragma unroll
    for (int i = 0; i < 4; i++) {
        const int r0 = bm + wm + i * 16 + tr;
        const int r1 = r0 + 8;
#pragma unroll
        for (int j = 0; j < 4; j++) {
            const int col = bn + wn + j * 8 + tc;
            const float b0 = bias[col], b1 = bias[col + 1];
            float v[4] = {acc[i][j][0] + b0, acc[i][j][1] + b1,
                          acc[i][j][2] + b0, acc[i][j][3] + b1};
#pragma unroll
            for (int r = 0; r < 4; r++) {
                if (ACT == 1)      v[r] = gelu_fast(v[r]);
                else if (ACT == 2) v[r] = sigmoid_fast(v[r]);
            }
            if (OUTMODE != 2) {
                *(float2*)(C + (size_t)r0 * N + col) = make_float2(v[0], v[1]);
                *(float2*)(C + (size_t)r1 * N + col) = make_float2(v[2], v[3]);
            }
            if (OUTMODE != 0) {
                *(__half2*)(ohi + (size_t)r0 * N + col) = __floats2half2_rn(v[0], v[1]);
                *(__half2*)(ohi + (size_t)r1 * N + col) = __floats2half2_rn(v[2], v[3]);
            }
        }
    }
}

// single-problem GEMM
template<int ACT, int OUTMODE>
__global__ void __launch_bounds__(256, 2)
gemm_mma(const __half* __restrict__ a0h, const __half* __restrict__ a1h, int Ks,
         const __half* __restrict__ bhp,
         const float* __restrict__ bias, float* __restrict__ C,
         __half* __restrict__ ohi,
         int M, int N, int K)
{
    gemm_body<ACT, OUTMODE>(a0h, a1h, Ks, bhp, bias, C, ohi, M, N, K,
                            blockIdx.y * 128, blockIdx.x * 128);
}

// dual-problem GEMM (z selects): both ACT=0, fp16-only out
__global__ void __launch_bounds__(256, 2)
gemm_mma_dual(const __half* __restrict__ aA, const __half* __restrict__ wA,
              const float* __restrict__ biasA, __half* __restrict__ outA, int KA,
              const __half* __restrict__ aB, const __half* __restrict__ wB,
              const float* __restrict__ biasB, __half* __restrict__ outB, int KB,
              int M, int N)
{
    const __half* a  = blockIdx.z ? aB   : aA;
    const __half* w  = blockIdx.z ? wB   : wA;
    const float* bi  = blockIdx.z ? biasB : biasA;
    __half* o        = blockIdx.z ? outB : outA;
    const int K      = blockIdx.z ? KB   : KA;
    gemm_body<0, 2>(a, a, K, w, bi, nullptr, o, M, N, K,
                    blockIdx.y * 128, blockIdx.x * 128);
}

// ---------------------------------------------------------------------------
// fused fp32 -> fp16 conversion over 6 buffers (sizes in float4 units).
// 2 independent float4s per thread (MLP=2), single 8B store per float4.
// ---------------------------------------------------------------------------
__device__ __forceinline__ void cvt_one(
    int t,
    const float* __restrict__ i0, __half* __restrict__ o0, int n0,
    const float* __restrict__ i1, __half* __restrict__ o1, int n1,
    const float* __restrict__ i2, __half* __restrict__ o2, int n2,
    const float* __restrict__ i3, __half* __restrict__ o3, int n3,
    const float* __restrict__ i4, __half* __restrict__ o4, int n4,
    const float* __restrict__ i5, __half* __restrict__ o5, int n5)
{
    const float* in; __half* out;
    if      (t < n0)                { in = i0; out = o0; }
    else if (t < n0+n1)             { t -= n0;             in = i1; out = o1; }
    else if (t < n0+n1+n2)          { t -= n0+n1;          in = i2; out = o2; }
    else if (t < n0+n1+n2+n3)       { t -= n0+n1+n2;       in = i3; out = o3; }
    else if (t < n0+n1+n2+n3+n4)    { t -= n0+n1+n2+n3;    in = i4; out = o4; }
    else if (t < n0+n1+n2+n3+n4+n5) { t -= n0+n1+n2+n3+n4; in = i5; out = o5; }
    else return;
    float4 v = ((const float4*)in)[t];
    __half2 lo = __floats2half2_rn(v.x, v.y);
    __half2 hi = __floats2half2_rn(v.z, v.w);
    uint2 u;
    u.x = *(const uint32_t*)&lo;
    u.y = *(const uint32_t*)&hi;
    ((uint2*)out)[t] = u;
}

__global__ void __launch_bounds__(256)
cvt6_kernel(const float* __restrict__ i0, __half* __restrict__ o0, int n0,
            const float* __restrict__ i1, __half* __restrict__ o1, int n1,
            const float* __restrict__ i2, __half* __restrict__ o2, int n2,
            const float* __restrict__ i3, __half* __restrict__ o3, int n3,
            const float* __restrict__ i4, __half* __restrict__ o4, int n4,
            const float* __restrict__ i5, __half* __restrict__ o5, int n5)
{
    const int base = blockIdx.x * 512 + threadIdx.x;
    cvt_one(base,       i0,o0,n0, i1,o1,n1, i2,o2,n2, i3,o3,n3, i4,o4,n4, i5,o5,n5);
    cvt_one(base + 256, i0,o0,n0, i1,o1,n1, i2,o2,n2, i3,o3,n3, i4,o4,n4, i5,o5,n5);
}

// ---------------------------------------------------------------------------
// 4-key attention; reads h/x_proj/q fp16; writes attn fp16.
// ---------------------------------------------------------------------------
__global__ void __launch_bounds__(256)
attn_kernel(const __half* __restrict__ h_prev, const __half* __restrict__ xproj,
            const __half* __restrict__ q, __half* __restrict__ ah)
{
    const int gw   = (blockIdx.x * 256 + threadIdx.x) >> 5;
    const int lane = threadIdx.x & 31;
    if (gw >= B_ * NH_) return;
    const size_t base = (size_t)(gw / NH_) * H_ + (size_t)(gw % NH_) * HD_ + lane * 16;

    const uint4* hp = (const uint4*)(h_prev + base);
    const uint4* xp = (const uint4*)(xproj + base);
    const uint4* qp = (const uint4*)(q + base);

    float hf[16], xf[16], qf[16];
#pragma unroll
    for (int k = 0; k < 2; k++) {
        uint4 uh = hp[k];
        uint4 ux = xp[k];
        uint4 uq = qp[k];
        const __half2* ph = (const __half2*)&uh;
        const __half2* px = (const __half2*)&ux;
        const __half2* pq = (const __half2*)&uq;
#pragma unroll
        for (int m = 0; m < 4; m++) {
            float2 th = __half22float2(ph[m]);
            float2 tx = __half22float2(px[m]);
            float2 tq = __half22float2(pq[m]);
            hf[8*k + 2*m] = th.x; hf[8*k + 2*m + 1] = th.y;
            xf[8*k + 2*m] = tx.x; xf[8*k + 2*m + 1] = tx.y;
            qf[8*k + 2*m] = tq.x; qf[8*k + 2*m + 1] = tq.y;
        }
    }

    float s0 = 0.f, s1 = 0.f, s3 = 0.f;
#pragma unroll
    for (int k = 0; k < 16; k++) {
        s0 += qf[k] * hf[k];
        s1 += qf[k] * xf[k];
        s3 += qf[k] * hf[k] * xf[k];
    }
#pragma unroll
    for (int off = 16; off > 0; off >>= 1) {
        s0 += __shfl_xor_sync(0xffffffffu, s0, off);
        s1 += __shfl_xor_sync(0xffffffffu, s1, off);
        s3 += __shfl_xor_sync(0xffffffffu, s3, off);
    }
    const float inv = rsqrtf((float)HD_);
    float sc0 = s0 * inv, sc1 = s1 * inv, sc2 = (s0 + s1) * inv, sc3 = s3 * inv;
    float m  = fmaxf(fmaxf(sc0, sc1), fmaxf(sc2, sc3));
    float e0 = expf(sc0 - m), e1 = expf(sc1 - m), e2 = expf(sc2 - m), e3 = expf(sc3 - m);
    float rs = 1.0f / (e0 + e1 + e2 + e3);
    float w0 = e0 * rs, w1 = e1 * rs, w2 = e2 * rs, w3 = e3 * rs;
    float ch = w0 + w2, cx = w1 + w2;

    __half2 oh[8];
#pragma unroll
    for (int k = 0; k < 8; k++) {
        float o0 = ch * hf[2*k]   + cx * xf[2*k]   + w3 * hf[2*k]   * xf[2*k];
        float o1 = ch * hf[2*k+1] + cx * xf[2*k+1] + w3 * hf[2*k+1] * xf[2*k+1];
        oh[k] = __floats2half2_rn(o0, o1);
    }
    uint4* op = (uint4*)(ah + base);
    op[0] = *(uint4*)&oh[0];
    op[1] = *(uint4*)&oh[4];
}

// ---------------------------------------------------------------------------
// LayerNorm + gated mix (attn_gelu fp16, gate fp16, h fp32)
// ---------------------------------------------------------------------------
__global__ void __launch_bounds__(256)
ln_gate_kernel(const __half* __restrict__ attn_g, const float* __restrict__ h_prev,
               const __half* __restrict__ gate, const float* __restrict__ gamma,
               const float* __restrict__ beta, float* __restrict__ out)
{
    const int b   = blockIdx.x;
    const int tid = threadIdx.x;
    const size_t rb = (size_t)b * H_;

    float4 y[2], h4[2];
    float sum = 0.f, sq = 0.f;
#pragma unroll
    for (int c = 0; c < 2; c++) {
        int d = c * 1024 + tid * 4;
        const __half2* ap = (const __half2*)(attn_g + rb + d);
        float2 a01 = __half22float2(ap[0]);
        float2 a23 = __half22float2(ap[1]);
        float4 hh = *(const float4*)(h_prev + rb + d);
        float4 yy = make_float4(a01.x + hh.x, a01.y + hh.y, a23.x + hh.z, a23.y + hh.w);
        y[c] = yy; h4[c] = hh;
        sum += yy.x + yy.y + yy.z + yy.w;
        sq  += yy.x * yy.x + yy.y * yy.y + yy.z * yy.z + yy.w * yy.w;
    }
#pragma unroll
    for (int off = 16; off > 0; off >>= 1) {
        sum += __shfl_xor_sync(0xffffffffu, sum, off);
        sq  += __shfl_xor_sync(0xffffffffu, sq,  off);
    }
    __shared__ float s_sum[8], s_sq[8];
    __shared__ float s_mu, s_rstd;
    if ((tid & 31) == 0) { s_sum[tid >> 5] = sum; s_sq[tid >> 5] = sq; }
    __syncthreads();
    if (tid == 0) {
        float S = 0.f, Q = 0.f;
#pragma unroll
        for (int i = 0; i < 8; i++) { S += s_sum[i]; Q += s_sq[i]; }
        float mu  = S / (float)H_;
        float var = Q / (float)H_ - mu * mu;
        s_mu = mu;
        s_rstd = rsqrtf(var + EPS_);
    }
    __syncthreads();
    const float mu = s_mu, rstd = s_rstd;

#pragma unroll
    for (int c = 0; c < 2; c++) {
        int d = c * 1024 + tid * 4;
        const __half2* gp = (const __half2*)(gate + rb + d);
        float2 g01 = __half22float2(gp[0]);
        float2 g23 = __half22float2(gp[1]);
        float4 gm = *(const float4*)(gamma + d);
        float4 bt = *(const float4*)(beta  + d);
        float4 yy = y[c], hh = h4[c], o;
        float c0 = (yy.x - mu) * rstd * gm.x + bt.x;
        float c1 = (yy.y - mu) * rstd * gm.y + bt.y;
        float c2 = (yy.z - mu) * rstd * gm.z + bt.z;
        float c3 = (yy.w - mu) * rstd * gm.w + bt.w;
        o.x = g01.x * c0 + (1.0f - g01.x) * hh.x;
        o.y = g01.y * c1 + (1.0f - g01.y) * hh.y;
        o.z = g23.x * c2 + (1.0f - g23.x) * hh.z;
        o.w = g23.y * c3 + (1.0f - g23.y) * hh.w;
        *(float4*)(out + rb + d) = o;
    }
}

// ---------------------------------------------------------------------------
extern "C" void kernel_launch(void* const* d_in, const int* in_sizes, int n_in,
                              void* d_out, int out_size)
{
    const float* h_prev = (const float*)d_in[0];
    const float* x      = (const float*)d_in[1];
    const float* W_proj = (const float*)d_in[2];
    const float* b_proj = (const float*)d_in[3];
    const float* W_q    = (const float*)d_in[4];
    const float* b_q    = (const float*)d_in[5];
    const float* W_o    = (const float*)d_in[6];
    const float* b_o    = (const float*)d_in[7];
    const float* W_g    = (const float*)d_in[8];
    const float* b_g    = (const float*)d_in[9];
    const float* gamma  = (const float*)d_in[10];
    const float* beta   = (const float*)d_in[11];
    float* out = (float*)d_out;

    __half *xsh, *hsh, *xph, *qh, *ath, *agh;
    __half *wph, *wqh, *woh, *wgh;
    cudaGetSymbolAddress((void**)&xsh, g_xs_h);
    cudaGetSymbolAddress((void**)&hsh, g_hs_h);
    cudaGetSymbolAddress((void**)&xph, g_xp_h);
    cudaGetSymbolAddress((void**)&qh,  g_q_h);
    cudaGetSymbolAddress((void**)&ath, g_at_h);
    cudaGetSymbolAddress((void**)&agh, g_ag_h);
    cudaGetSymbolAddress((void**)&wph, g_wp_h);
    cudaGetSymbolAddress((void**)&wqh, g_wq_h);
    cudaGetSymbolAddress((void**)&woh, g_wo_h);
    cudaGetSymbolAddress((void**)&wgh, g_wg_h);

    cudaFuncSetAttribute(gemm_mma_dual,  cudaFuncAttributeMaxDynamicSharedMemorySize, SMEM_BYTES);
    cudaFuncSetAttribute(gemm_mma<1, 2>, cudaFuncAttributeMaxDynamicSharedMemorySize, SMEM_BYTES);
    cudaFuncSetAttribute(gemm_mma<2, 2>, cudaFuncAttributeMaxDynamicSharedMemorySize, SMEM_BYTES);

    // --- launch #0: ALL conversions fused (weights + activations) ---
    {
        int n0 = H_ * IN_ / 4;       // W_proj
        int n1 = H_ * H_ / 4;        // W_q
        int n2 = H_ * H_ / 4;        // W_o
        int n3 = H_ * 2 * H_ / 4;    // W_g
        int n4 = B_ * IN_ / 4;       // x
        int n5 = B_ * H_ / 4;        // h_prev
        int nt = n0 + n1 + n2 + n3 + n4 + n5;
        cvt6_kernel<<<(nt + 511) / 512, 256>>>(
            W_proj, wph, n0, W_q, wqh, n1, W_o, woh, n2,
            W_g, wgh, n3, x, xsh, n4, h_prev, hsh, n5);
    }

    dim3 grid2(H_ / 128, B_ / 128, 2);   // merged x_proj + q: 2048 CTAs
    dim3 grid(H_ / 128, B_ / 128);       // 1024 CTAs

    // #1) merged: z=0 -> x_proj (K=1024), z=1 -> q (K=2048)
    gemm_mma_dual<<<grid2, 256, SMEM_BYTES>>>(
        xsh, wph, b_proj, xph, IN_,
        hsh, wqh, b_q,    qh,  H_,
        B_, H_);
    // #2) attention -> attn fp16 (all-fp16 reads)
    attn_kernel<<<(B_ * NH_) / 8, 256>>>(hsh, xph, qh, ath);
    // #3) attn_gelu (fp16 only)
    gemm_mma<1, 2><<<grid, 256, SMEM_BYTES>>>(
        ath, ath, H_, woh, b_o, nullptr, agh, B_, H_, H_);
    // #4) gate (fp16 only, reuses q buffer)
    gemm_mma<2, 2><<<grid, 256, SMEM_BYTES>>>(
        hsh, agh, H_, wgh, b_g, nullptr, qh, B_, H_, 2 * H_);
    // #5) layernorm + gated mix (ag fp16, gate fp16, h fp32)
    ln_gate_kernel<<<B_, 256>>>(agh, h_prev, qh, gamma, beta, out);
}

// round 17
// speedup vs baseline: 1.5564x; 1.0001x over previous
#include <cuda_runtime.h>
#include <cuda_fp16.h>
#include <math.h>
#include <stdint.h>

#define B_  8192
#define IN_ 1024
#define H_  2048
#define NH_ 4
#define HD_ 512
#define EPS_ 1e-5f

// ---------------------------------------------------------------------------
// Device scratch (allocation-free rule)
// ---------------------------------------------------------------------------
// fp16 activations / intermediates
__device__ __align__(128) __half g_xs_h[(size_t)B_ * IN_];   // x fp16
__device__ __align__(128) __half g_hs_h[(size_t)B_ * H_];    // h_prev fp16
__device__ __align__(128) __half g_xp_h[(size_t)B_ * H_];    // x_proj fp16
__device__ __align__(128) __half g_q_h [(size_t)B_ * H_];    // q fp16 -> gate fp16
__device__ __align__(128) __half g_at_h[(size_t)B_ * H_];    // attn fp16
__device__ __align__(128) __half g_ag_h[(size_t)B_ * H_];    // attn_gelu fp16

// fp16 weights
__device__ __align__(128) __half g_wp_h[(size_t)H_ * IN_];
__device__ __align__(128) __half g_wq_h[(size_t)H_ * H_];
__device__ __align__(128) __half g_wo_h[(size_t)H_ * H_];
__device__ __align__(128) __half g_wg_h[(size_t)H_ * 2 * H_];

// ---------------------------------------------------------------------------
// PTX helpers (base-target-safe)
// ---------------------------------------------------------------------------
__device__ __forceinline__ uint32_t smem_u32(const void* p) {
    uint32_t a;
    asm("{ .reg .u64 t; cvta.to.shared.u64 t, %1; cvt.u32.u64 %0, t; }" : "=r"(a) : "l"(p));
    return a;
}

#define CP_ASYNC16(sa, ga) \
    asm volatile("cp.async.cg.shared.global [%0], [%1], 16;\n" :: "r"(sa), "l"(ga))
#define CP_COMMIT()  asm volatile("cp.async.commit_group;\n" ::: "memory")

#define LDSM_X4(r0, r1, r2, r3, addr) \
    asm volatile("ldmatrix.sync.aligned.m8n8.x4.shared.b16 {%0,%1,%2,%3}, [%4];" \
        : "=r"(r0), "=r"(r1), "=r"(r2), "=r"(r3) : "r"(addr))

#define MMA_F16(c0, c1, c2, c3, a0, a1, a2, a3, b0, b1) \
    asm volatile("mma.sync.aligned.m16n8k16.row.col.f32.f16.f16.f32 " \
        "{%0,%1,%2,%3}, {%4,%5,%6,%7}, {%8,%9}, {%0,%1,%2,%3};" \
        : "+f"(c0), "+f"(c1), "+f"(c2), "+f"(c3) \
        : "r"(a0), "r"(a1), "r"(a2), "r"(a3), "r"(b0), "r"(b1))

// fast exact-GELU: Abramowitz-Stegun 7.1.26 erf (|abs err| <= 1.5e-7) + __expf
__device__ __forceinline__ float gelu_fast(float v) {
    float s  = v * 0.70710678118654752f;
    float ax = fabsf(s);
    float t  = __fdividef(1.0f, fmaf(0.3275911f, ax, 1.0f));
    float p  = fmaf(fmaf(fmaf(fmaf(1.061405429f, t, -1.453152027f), t,
                               1.421413741f), t, -0.284496736f), t, 0.254829592f) * t;
    float er = 1.0f - p * __expf(-ax * ax);
    er = copysignf(er, s);
    return 0.5f * v * (1.0f + er);
}
__device__ __forceinline__ float sigmoid_fast(float v) {
    return __fdividef(1.0f, 1.0f + __expf(-v));
}

// ---------------------------------------------------------------------------
// SMEM: per stage: A 128x64 fp16, B 128x64 fp16, row stride 72 elems (144B).
// 3 stages = 108 KB -> 2 CTA/SM.
// ---------------------------------------------------------------------------
#define SSTR 72
#define T_ELEMS (128 * SSTR)               // 9216
#define OFF_A 0
#define OFF_B T_ELEMS
#define STAGE_ELEMS (2 * T_ELEMS)          // 18432
#define NSTAGE 3
#define SMEM_BYTES (NSTAGE * STAGE_ELEMS * 2)   // 110592

// ---------------------------------------------------------------------------
// GEMM body: CTA 128x128, 8 warps (warp tile 64x32), K-chunk 64, 3 stages.
// Both B-LDSMs hoisted above the MMA block per ks (latency hiding).
// ---------------------------------------------------------------------------
template<int ACT, int OUTMODE>   // OUTMODE: 0 fp32, 1 both, 2 fp16
__device__ __forceinline__ void gemm_body(
    const __half* __restrict__ a0h, const __half* __restrict__ a1h, int Ks,
    const __half* __restrict__ bhp,
    const float* __restrict__ bias, float* __restrict__ C,
    __half* __restrict__ ohi,
    int M, int N, int K, int bm, int bn)
{
    extern __shared__ __align__(128) char smem[];
    const uint32_t sbase = smem_u32(smem);
    const int tid  = threadIdx.x;
    const int warp = tid >> 5;
    const int lane = tid & 31;
    const int wm = (warp >> 2) * 64;       // 0 or 64
    const int wn = (warp & 3) * 32;        // 0..96

    float acc[4][4][4];
#pragma unroll
    for (int i = 0; i < 4; i++)
#pragma unroll
        for (int j = 0; j < 4; j++)
#pragma unroll
            for (int r = 0; r < 4; r++) acc[i][j][r] = 0.0f;

    const int nk = K / 64;

    auto load_stage = [&](int stage, int k0) {
        const __half* ah;
        int lda, kk;
        if (k0 < Ks) { ah = a0h; lda = Ks;     kk = k0; }
        else         { ah = a1h; lda = K - Ks; kk = k0 - Ks; }
        const uint32_t stb = sbase + (uint32_t)stage * STAGE_ELEMS * 2;
#pragma unroll
        for (int r = 0; r < 4; r++) {
            const int c   = tid + r * 256;        // 0..1023
            const int row = c >> 3;
            const int seg = c & 7;
            const uint32_t so = stb + (uint32_t)(row * SSTR + seg * 8) * 2;
            CP_ASYNC16(so + OFF_A * 2, ah  + (size_t)(bm + row) * lda + kk + seg * 8);
            CP_ASYNC16(so + OFF_B * 2, bhp + (size_t)(bn + row) * K   + k0 + seg * 8);
        }
        CP_COMMIT();
    };

    const int lrow = (lane & 7) + ((lane >> 3) & 1) * 8;   // 0..15
    const int lcol = (lane >> 4) * 8;                      // 0 or 8
    uint32_t aoff[4], boff[2];
#pragma unroll
    for (int i = 0; i < 4; i++)
        aoff[i] = (uint32_t)(((wm + i * 16 + lrow) * SSTR + lcol) * 2) + OFF_A * 2;
#pragma unroll
    for (int p = 0; p < 2; p++)
        boff[p] = (uint32_t)(((wn + p * 16 + lrow) * SSTR + lcol) * 2) + OFF_B * 2;

    load_stage(0, 0);
    if (nk > 1) load_stage(1, 64);

    int st_comp = 0;
    int st_load = 2;

    for (int kc = 0; kc < nk; kc++) {
        if (kc + 1 < nk) asm volatile("cp.async.wait_group 1;\n" ::: "memory");
        else             asm volatile("cp.async.wait_group 0;\n" ::: "memory");
        __syncthreads();

        if (kc + 2 < nk) load_stage(st_load, (kc + 2) * 64);

        const uint32_t stb = sbase + (uint32_t)st_comp * STAGE_ELEMS * 2;
        uint32_t ba[4], bb[2];
#pragma unroll
        for (int i = 0; i < 4; i++) ba[i] = stb + aoff[i];
#pragma unroll
        for (int p = 0; p < 2; p++) bb[p] = stb + boff[p];

#pragma unroll
        for (int ks = 0; ks < 4; ks++) {
            uint32_t ah[4][4];
#pragma unroll
            for (int i = 0; i < 4; i++)
                LDSM_X4(ah[i][0], ah[i][1], ah[i][2], ah[i][3], ba[i] + ks * 32);
            // hoist BOTH B ldmatrix ops before the MMA block:
            // B(p1) latency hides under p0's MMAs.
            uint32_t b00, b01, b02, b03, b10, b11, b12, b13;
            LDSM_X4(b00, b01, b02, b03, bb[0] + ks * 32);
            LDSM_X4(b10, b11, b12, b13, bb[1] + ks * 32);
#pragma unroll
            for (int i = 0; i < 4; i++) {
                float* c0 = acc[i][0];
                float* c1 = acc[i][1];
                MMA_F16(c0[0], c0[1], c0[2], c0[3],
                        ah[i][0], ah[i][1], ah[i][2], ah[i][3], b00, b02);
                MMA_F16(c1[0], c1[1], c1[2], c1[3],
                        ah[i][0], ah[i][1], ah[i][2], ah[i][3], b01, b03);
            }
#pragma unroll
            for (int i = 0; i < 4; i++) {
                float* c2 = acc[i][2];
                float* c3 = acc[i][3];
                MMA_F16(c2[0], c2[1], c2[2], c2[3],
                        ah[i][0], ah[i][1], ah[i][2], ah[i][3], b10, b12);
                MMA_F16(c3[0], c3[1], c3[2], c3[3],
                        ah[i][0], ah[i][1], ah[i][2], ah[i][3], b11, b13);
            }
        }
        st_comp = (st_comp == NSTAGE - 1) ? 0 : st_comp + 1;
        st_load = (st_load == NSTAGE - 1) ? 0 : st_load + 1;
    }

    // ---- epilogue ----
    const int tr = lane >> 2;
    const int tc = (lane & 3) * 2;
#pragma unroll
    for (int i = 0; i < 4; i++) {
        const int r0 = bm + wm + i * 16 + tr;
        const int r1 = r0 + 8;
#pragma unroll
        for (int j = 0; j < 4; j++) {
            const int col = bn + wn + j * 8 + tc;
            const float b0 = bias[col], b1 = bias[col + 1];
            float v[4] = {acc[i][j][0] + b0, acc[i][j][1] + b1,
                          acc[i][j][2] + b0, acc[i][j][3] + b1};
#pragma unroll
            for (int r = 0; r < 4; r++) {
                if (ACT == 1)      v[r] = gelu_fast(v[r]);
                else if (ACT == 2) v[r] = sigmoid_fast(v[r]);
            }
            if (OUTMODE != 2) {
                *(float2*)(C + (size_t)r0 * N + col) = make_float2(v[0], v[1]);
                *(float2*)(C + (size_t)r1 * N + col) = make_float2(v[2], v[3]);
            }
            if (OUTMODE != 0) {
                *(__half2*)(ohi + (size_t)r0 * N + col) = __floats2half2_rn(v[0], v[1]);
                *(__half2*)(ohi + (size_t)r1 * N + col) = __floats2half2_rn(v[2], v[3]);
            }
        }
    }
}

// single-problem GEMM
template<int ACT, int OUTMODE>
__global__ void __launch_bounds__(256, 2)
gemm_mma(const __half* __restrict__ a0h, const __half* __restrict__ a1h, int Ks,
         const __half* __restrict__ bhp,
         const float* __restrict__ bias, float* __restrict__ C,
         __half* __restrict__ ohi,
         int M, int N, int K)
{
    gemm_body<ACT, OUTMODE>(a0h, a1h, Ks, bhp, bias, C, ohi, M, N, K,
                            blockIdx.y * 128, blockIdx.x * 128);
}

// dual-problem GEMM (z selects): both ACT=0, fp16-only out
__global__ void __launch_bounds__(256, 2)
gemm_mma_dual(const __half* __restrict__ aA, const __half* __restrict__ wA,
              const float* __restrict__ biasA, __half* __restrict__ outA, int KA,
              const __half* __restrict__ aB, const __half* __restrict__ wB,
              const float* __restrict__ biasB, __half* __restrict__ outB, int KB,
              int M, int N)
{
    const __half* a  = blockIdx.z ? aB   : aA;
    const __half* w  = blockIdx.z ? wB   : wA;
    const float* bi  = blockIdx.z ? biasB : biasA;
    __half* o        = blockIdx.z ? outB : outA;
    const int K      = blockIdx.z ? KB   : KA;
    gemm_body<0, 2>(a, a, K, w, bi, nullptr, o, M, N, K,
                    blockIdx.y * 128, blockIdx.x * 128);
}

// ---------------------------------------------------------------------------
// fused fp32 -> fp16 conversion over 6 buffers (sizes in float4 units).
// 2 independent float4s per thread (MLP=2), single 8B store per float4.
// ---------------------------------------------------------------------------
__device__ __forceinline__ void cvt_one(
    int t,
    const float* __restrict__ i0, __half* __restrict__ o0, int n0,
    const float* __restrict__ i1, __half* __restrict__ o1, int n1,
    const float* __restrict__ i2, __half* __restrict__ o2, int n2,
    const float* __restrict__ i3, __half* __restrict__ o3, int n3,
    const float* __restrict__ i4, __half* __restrict__ o4, int n4,
    const float* __restrict__ i5, __half* __restrict__ o5, int n5)
{
    const float* in; __half* out;
    if      (t < n0)                { in = i0; out = o0; }
    else if (t < n0+n1)             { t -= n0;             in = i1; out = o1; }
    else if (t < n0+n1+n2)          { t -= n0+n1;          in = i2; out = o2; }
    else if (t < n0+n1+n2+n3)       { t -= n0+n1+n2;       in = i3; out = o3; }
    else if (t < n0+n1+n2+n3+n4)    { t -= n0+n1+n2+n3;    in = i4; out = o4; }
    else if (t < n0+n1+n2+n3+n4+n5) { t -= n0+n1+n2+n3+n4; in = i5; out = o5; }
    else return;
    float4 v = ((const float4*)in)[t];
    __half2 lo = __floats2half2_rn(v.x, v.y);
    __half2 hi = __floats2half2_rn(v.z, v.w);
    uint2 u;
    u.x = *(const uint32_t*)&lo;
    u.y = *(const uint32_t*)&hi;
    ((uint2*)out)[t] = u;
}

__global__ void __launch_bounds__(256)
cvt6_kernel(const float* __restrict__ i0, __half* __restrict__ o0, int n0,
            const float* __restrict__ i1, __half* __restrict__ o1, int n1,
            const float* __restrict__ i2, __half* __restrict__ o2, int n2,
            const float* __restrict__ i3, __half* __restrict__ o3, int n3,
            const float* __restrict__ i4, __half* __restrict__ o4, int n4,
            const float* __restrict__ i5, __half* __restrict__ o5, int n5)
{
    const int base = blockIdx.x * 512 + threadIdx.x;
    cvt_one(base,       i0,o0,n0, i1,o1,n1, i2,o2,n2, i3,o3,n3, i4,o4,n4, i5,o5,n5);
    cvt_one(base + 256, i0,o0,n0, i1,o1,n1, i2,o2,n2, i3,o3,n3, i4,o4,n4, i5,o5,n5);
}

// ---------------------------------------------------------------------------
// 4-key attention; reads h/x_proj/q fp16; writes attn fp16.
// ---------------------------------------------------------------------------
__global__ void __launch_bounds__(256)
attn_kernel(const __half* __restrict__ h_prev, const __half* __restrict__ xproj,
            const __half* __restrict__ q, __half* __restrict__ ah)
{
    const int gw   = (blockIdx.x * 256 + threadIdx.x) >> 5;
    const int lane = threadIdx.x & 31;
    if (gw >= B_ * NH_) return;
    const size_t base = (size_t)(gw / NH_) * H_ + (size_t)(gw % NH_) * HD_ + lane * 16;

    const uint4* hp = (const uint4*)(h_prev + base);
    const uint4* xp = (const uint4*)(xproj + base);
    const uint4* qp = (const uint4*)(q + base);

    float hf[16], xf[16], qf[16];
#pragma unroll
    for (int k = 0; k < 2; k++) {
        uint4 uh = hp[k];
        uint4 ux = xp[k];
        uint4 uq = qp[k];
        const __half2* ph = (const __half2*)&uh;
        const __half2* px = (const __half2*)&ux;
        const __half2* pq = (const __half2*)&uq;
#pragma unroll
        for (int m = 0; m < 4; m++) {
            float2 th = __half22float2(ph[m]);
            float2 tx = __half22float2(px[m]);
            float2 tq = __half22float2(pq[m]);
            hf[8*k + 2*m] = th.x; hf[8*k + 2*m + 1] = th.y;
            xf[8*k + 2*m] = tx.x; xf[8*k + 2*m + 1] = tx.y;
            qf[8*k + 2*m] = tq.x; qf[8*k + 2*m + 1] = tq.y;
        }
    }

    float s0 = 0.f, s1 = 0.f, s3 = 0.f;
#pragma unroll
    for (int k = 0; k < 16; k++) {
        s0 += qf[k] * hf[k];
        s1 += qf[k] * xf[k];
        s3 += qf[k] * hf[k] * xf[k];
    }
#pragma unroll
    for (int off = 16; off > 0; off >>= 1) {
        s0 += __shfl_xor_sync(0xffffffffu, s0, off);
        s1 += __shfl_xor_sync(0xffffffffu, s1, off);
        s3 += __shfl_xor_sync(0xffffffffu, s3, off);
    }
    const float inv = rsqrtf((float)HD_);
    float sc0 = s0 * inv, sc1 = s1 * inv, sc2 = (s0 + s1) * inv, sc3 = s3 * inv;
    float m  = fmaxf(fmaxf(sc0, sc1), fmaxf(sc2, sc3));
    float e0 = expf(sc0 - m), e1 = expf(sc1 - m), e2 = expf(sc2 - m), e3 = expf(sc3 - m);
    float rs = 1.0f / (e0 + e1 + e2 + e3);
    float w0 = e0 * rs, w1 = e1 * rs, w2 = e2 * rs, w3 = e3 * rs;
    float ch = w0 + w2, cx = w1 + w2;

    __half2 oh[8];
#pragma unroll
    for (int k = 0; k < 8; k++) {
        float o0 = ch * hf[2*k]   + cx * xf[2*k]   + w3 * hf[2*k]   * xf[2*k];
        float o1 = ch * hf[2*k+1] + cx * xf[2*k+1] + w3 * hf[2*k+1] * xf[2*k+1];
        oh[k] = __floats2half2_rn(o0, o1);
    }
    uint4* op = (uint4*)(ah + base);
    op[0] = *(uint4*)&oh[0];
    op[1] = *(uint4*)&oh[4];
}

// ---------------------------------------------------------------------------
// LayerNorm + gated mix (attn_gelu fp16, gate fp16, h fp32)
// ---------------------------------------------------------------------------
__global__ void __launch_bounds__(256)
ln_gate_kernel(const __half* __restrict__ attn_g, const float* __restrict__ h_prev,
               const __half* __restrict__ gate, const float* __restrict__ gamma,
               const float* __restrict__ beta, float* __restrict__ out)
{
    const int b   = blockIdx.x;
    const int tid = threadIdx.x;
    const size_t rb = (size_t)b * H_;

    float4 y[2], h4[2];
    float sum = 0.f, sq = 0.f;
#pragma unroll
    for (int c = 0; c < 2; c++) {
        int d = c * 1024 + tid * 4;
        const __half2* ap = (const __half2*)(attn_g + rb + d);
        float2 a01 = __half22float2(ap[0]);
        float2 a23 = __half22float2(ap[1]);
        float4 hh = *(const float4*)(h_prev + rb + d);
        float4 yy = make_float4(a01.x + hh.x, a01.y + hh.y, a23.x + hh.z, a23.y + hh.w);
        y[c] = yy; h4[c] = hh;
        sum += yy.x + yy.y + yy.z + yy.w;
        sq  += yy.x * yy.x + yy.y * yy.y + yy.z * yy.z + yy.w * yy.w;
    }
#pragma unroll
    for (int off = 16; off > 0; off >>= 1) {
        sum += __shfl_xor_sync(0xffffffffu, sum, off);
        sq  += __shfl_xor_sync(0xffffffffu, sq,  off);
    }
    __shared__ float s_sum[8], s_sq[8];
    __shared__ float s_mu, s_rstd;
    if ((tid & 31) == 0) { s_sum[tid >> 5] = sum; s_sq[tid >> 5] = sq; }
    __syncthreads();
    if (tid == 0) {
        float S = 0.f, Q = 0.f;
#pragma unroll
        for (int i = 0; i < 8; i++) { S += s_sum[i]; Q += s_sq[i]; }
        float mu  = S / (float)H_;
        float var = Q / (float)H_ - mu * mu;
        s_mu = mu;
        s_rstd = rsqrtf(var + EPS_);
    }
    __syncthreads();
    const float mu = s_mu, rstd = s_rstd;

#pragma unroll
    for (int c = 0; c < 2; c++) {
        int d = c * 1024 + tid * 4;
        const __half2* gp = (const __half2*)(gate + rb + d);
        float2 g01 = __half22float2(gp[0]);
        float2 g23 = __half22float2(gp[1]);
        float4 gm = *(const float4*)(gamma + d);
        float4 bt = *(const float4*)(beta  + d);
        float4 yy = y[c], hh = h4[c], o;
        float c0 = (yy.x - mu) * rstd * gm.x + bt.x;
        float c1 = (yy.y - mu) * rstd * gm.y + bt.y;
        float c2 = (yy.z - mu) * rstd * gm.z + bt.z;
        float c3 = (yy.w - mu) * rstd * gm.w + bt.w;
        o.x = g01.x * c0 + (1.0f - g01.x) * hh.x;
        o.y = g01.y * c1 + (1.0f - g01.y) * hh.y;
        o.z = g23.x * c2 + (1.0f - g23.x) * hh.z;
        o.w = g23.y * c3 + (1.0f - g23.y) * hh.w;
        *(float4*)(out + rb + d) = o;
    }
}

// ---------------------------------------------------------------------------
extern "C" void kernel_launch(void* const* d_in, const int* in_sizes, int n_in,
                              void* d_out, int out_size)
{
    const float* h_prev = (const float*)d_in[0];
    const float* x      = (const float*)d_in[1];
    const float* W_proj = (const float*)d_in[2];
    const float* b_proj = (const float*)d_in[3];
    const float* W_q    = (const float*)d_in[4];
    const float* b_q    = (const float*)d_in[5];
    const float* W_o    = (const float*)d_in[6];
    const float* b_o    = (const float*)d_in[7];
    const float* W_g    = (const float*)d_in[8];
    const float* b_g    = (const float*)d_in[9];
    const float* gamma  = (const float*)d_in[10];
    const float* beta   = (const float*)d_in[11];
    float* out = (float*)d_out;

    __half *xsh, *hsh, *xph, *qh, *ath, *agh;
    __half *wph, *wqh, *woh, *wgh;
    cudaGetSymbolAddress((void**)&xsh, g_xs_h);
    cudaGetSymbolAddress((void**)&hsh, g_hs_h);
    cudaGetSymbolAddress((void**)&xph, g_xp_h);
    cudaGetSymbolAddress((void**)&qh,  g_q_h);
    cudaGetSymbolAddress((void**)&ath, g_at_h);
    cudaGetSymbolAddress((void**)&agh, g_ag_h);
    cudaGetSymbolAddress((void**)&wph, g_wp_h);
    cudaGetSymbolAddress((void**)&wqh, g_wq_h);
    cudaGetSymbolAddress((void**)&woh, g_wo_h);
    cudaGetSymbolAddress((void**)&wgh, g_wg_h);

    cudaFuncSetAttribute(gemm_mma_dual,  cudaFuncAttributeMaxDynamicSharedMemorySize, SMEM_BYTES);
    cudaFuncSetAttribute(gemm_mma<1, 2>, cudaFuncAttributeMaxDynamicSharedMemorySize, SMEM_BYTES);
    cudaFuncSetAttribute(gemm_mma<2, 2>, cudaFuncAttributeMaxDynamicSharedMemorySize, SMEM_BYTES);

    // --- launch #0: ALL conversions fused (weights + activations) ---
    {
        int n0 = H_ * IN_ / 4;       // W_proj
        int n1 = H_ * H_ / 4;        // W_q
        int n2 = H_ * H_ / 4;        // W_o
        int n3 = H_ * 2 * H_ / 4;    // W_g
        int n4 = B_ * IN_ / 4;       // x
        int n5 = B_ * H_ / 4;        // h_prev
        int nt = n0 + n1 + n2 + n3 + n4 + n5;
        cvt6_kernel<<<(nt + 511) / 512, 256>>>(
            W_proj, wph, n0, W_q, wqh, n1, W_o, woh, n2,
            W_g, wgh, n3, x, xsh, n4, h_prev, hsh, n5);
    }

    dim3 grid2(H_ / 128, B_ / 128, 2);   // merged x_proj + q: 2048 CTAs
    dim3 grid(H_ / 128, B_ / 128);       // 1024 CTAs

    // #1) merged: z=0 -> x_proj (K=1024), z=1 -> q (K=2048)
    gemm_mma_dual<<<grid2, 256, SMEM_BYTES>>>(
        xsh, wph, b_proj, xph, IN_,
        hsh, wqh, b_q,    qh,  H_,
        B_, H_);
    // #2) attention -> attn fp16 (all-fp16 reads)
    attn_kernel<<<(B_ * NH_) / 8, 256>>>(hsh, xph, qh, ath);
    // #3) attn_gelu (fp16 only)
    gemm_mma<1, 2><<<grid, 256, SMEM_BYTES>>>(
        ath, ath, H_, woh, b_o, nullptr, agh, B_, H_, H_);
    // #4) gate (fp16 only, reuses q buffer)
    gemm_mma<2, 2><<<grid, 256, SMEM_BYTES>>>(
        hsh, agh, H_, wgh, b_g, nullptr, qh, B_, H_, 2 * H_);
    // #5) layernorm + gated mix (ag fp16, gate fp16, h fp32)
    ln_gate_kernel<<<B_, 256>>>(agh, h_prev, qh, gamma, beta, out);
}